// round 16
// baseline (speedup 1.0000x reference)
#include <cuda_runtime.h>

#define S   32768          // 32*32*32 spatial
#define NB  2              // batch
#define CIN 64
#define CM  32             // mid channels
#define KCH 216            // dynamic kernel channels
#define NG  8              // groups
#define CPG 8              // channels per group (64/8)

typedef unsigned long long u64;

// ---------------- f32x2 helpers ----------------
__device__ __forceinline__ u64 pk2(float a, float b) {
    u64 r; asm("mov.b64 %0,{%1,%2};" : "=l"(r) : "f"(a), "f"(b)); return r;
}
__device__ __forceinline__ void upk2(u64 v, float& a, float& b) {
    asm("mov.b64 {%0,%1},%2;" : "=f"(a), "=f"(b) : "l"(v));
}
__device__ __forceinline__ void fma2(u64& d, u64 a, u64 b) {
    asm("fma.rn.f32x2 %0,%1,%2,%0;" : "+l"(d) : "l"(a), "l"(b));
}

// ---------------- scratch (device globals; allocation-free) ----------------
__device__ float g_a1[NB * CM  * S];
__device__ float g_a2[NB * CM  * S];
__device__ float g_wk[NB * KCH * S];
__device__ float g_y [NB * CIN * S];
__device__ float g_h [NB * 128 * S];
__device__ float g_sum[NB * NG];       // zero-init; k4 re-zeros after use
__device__ float g_sq [NB * NG];
__device__ float g_mu [NB * NG];
__device__ float g_rstd[NB * NG];

// ---------------- cv body: K->32 1x1 conv + BN + ReLU (R15 passing) ----------
template<int K>
__device__ __forceinline__ void cv_body(
        const float* __restrict__ in, const float* __restrict__ w,
        const float* __restrict__ sc, const float* __restrict__ bi,
        float* __restrict__ outbuf) {
    __shared__ u64 ws[K * 32];       // [c][o]
    int t = threadIdx.x;
    for (int i = t; i < K * 32; i += 256) {
        int c = i >> 5, o = i & 31;
        float v = w[o * K + c];
        ws[i] = pk2(v, v);
    }
    __syncthreads();

    int warp = t >> 5, lane = t & 31;
    int og = warp & 1, pset = warp >> 1;
    int pr = pset * 32 + lane;
    int pos0 = blockIdx.x * 512;
    int b = pos0 >> 15, s = pos0 & (S - 1);
    int sA = s + 2 * pr;
    int sB = sA + 256;

    u64 accA[16], accB[16];
#pragma unroll
    for (int o = 0; o < 16; o++) { accA[o] = 0ull; accB[o] = 0ull; }

    const float* ib = in + b * K * S;
#pragma unroll 2
    for (int c = 0; c < K; c++) {
        u64 xqA = *(const u64*)(ib + c * S + sA);
        u64 xqB = *(const u64*)(ib + c * S + sB);
        const ulonglong2* wv = (const ulonglong2*)(ws + c * 32 + og * 16);
#pragma unroll
        for (int j = 0; j < 8; j++) {
            ulonglong2 wq = wv[j];
            fma2(accA[2 * j], wq.x, xqA);
            fma2(accB[2 * j], wq.x, xqB);
            fma2(accA[2 * j + 1], wq.y, xqA);
            fma2(accB[2 * j + 1], wq.y, xqB);
        }
    }
#pragma unroll
    for (int o = 0; o < 16; o++) {
        int oo = og * 16 + o;
        float scv = __ldg(sc + oo), biv = __ldg(bi + oo);
        float a, bq;
        float* ob = outbuf + (b * CM + oo) * S;
        upk2(accA[o], a, bq);
        *(u64*)(ob + sA) = pk2(fmaxf(a * scv + biv, 0.f), fmaxf(bq * scv + biv, 0.f));
        upk2(accB[o], a, bq);
        *(u64*)(ob + sB) = pk2(fmaxf(a * scv + biv, 0.f), fmaxf(bq * scv + biv, 0.f));
    }
}

__global__ void __launch_bounds__(256) k1_cv1(
        const float* __restrict__ x, const float* __restrict__ w1,
        const float* __restrict__ s1, const float* __restrict__ b1) {
    cv_body<64>(x, w1, s1, b1, g_a1);
}

__global__ void __launch_bounds__(256) k3a_cv3(
        const float* __restrict__ w3, const float* __restrict__ s3,
        const float* __restrict__ b3) {
    cv_body<32>(g_a2, w3, s3, b3, g_a1);
}

// ---------------- k2: depthwise 5x5x5 (zero pad) + BN, f32x2 (passing) ------
__global__ void __launch_bounds__(128) k2_dw5(
        const float* __restrict__ w2, const float* __restrict__ s2,
        const float* __restrict__ b2) {
    int blk = blockIdx.x;
    int d = blk & 31;
    int c = (blk >> 5) & 31;
    int b = blk >> 10;
    int t = threadIdx.x;
    int wq = t & 3, h = t >> 2;
    int w0 = wq * 8;

    const float* src = g_a1 + (b * CM + c) * S;
    const float* wc  = w2 + c * 125;
    const float4 zero4 = make_float4(0.f, 0.f, 0.f, 0.f);

    u64 acc[4];
#pragma unroll
    for (int m = 0; m < 4; m++) acc[m] = 0ull;

    for (int dd = 0; dd < 5; dd++) {
        int zd = d + dd - 2;
        if ((unsigned)zd >= 32u) continue;
        for (int dh = 0; dh < 5; dh++) {
            int zh = h + dh - 2;
            if ((unsigned)zh >= 32u) continue;
            const float* row = src + (zd * 32 + zh) * 32;
            float4 f0 = (wq > 0) ? *(const float4*)(row + w0 - 4) : zero4;
            float4 f1 = *(const float4*)(row + w0);
            float4 f2 = *(const float4*)(row + w0 + 4);
            float4 f3 = (wq < 3) ? *(const float4*)(row + w0 + 8) : zero4;
            u64 A0 = pk2(f0.z, f0.w), A1 = pk2(f1.x, f1.y), A2 = pk2(f1.z, f1.w);
            u64 A3 = pk2(f2.x, f2.y), A4 = pk2(f2.z, f2.w), A5 = pk2(f3.x, f3.y);
            u64 M0 = pk2(f0.w, f1.x), M1 = pk2(f1.y, f1.z), M2 = pk2(f1.w, f2.x);
            u64 M3 = pk2(f2.y, f2.z), M4 = pk2(f2.w, f3.x);
            const float* wr = wc + (dd * 5 + dh) * 5;
            u64 T0 = pk2(wr[0], wr[0]), T1 = pk2(wr[1], wr[1]), T2 = pk2(wr[2], wr[2]);
            u64 T3 = pk2(wr[3], wr[3]), T4 = pk2(wr[4], wr[4]);
            fma2(acc[0], T0, A0); fma2(acc[0], T1, M0); fma2(acc[0], T2, A1);
            fma2(acc[0], T3, M1); fma2(acc[0], T4, A2);
            fma2(acc[1], T0, A1); fma2(acc[1], T1, M1); fma2(acc[1], T2, A2);
            fma2(acc[1], T3, M2); fma2(acc[1], T4, A3);
            fma2(acc[2], T0, A2); fma2(acc[2], T1, M2); fma2(acc[2], T2, A3);
            fma2(acc[2], T3, M3); fma2(acc[2], T4, A4);
            fma2(acc[3], T0, A3); fma2(acc[3], T1, M3); fma2(acc[3], T2, A4);
            fma2(acc[3], T3, M4); fma2(acc[3], T4, A5);
        }
    }
    float scv = s2[c], biv = b2[c];
    float* dst = g_a2 + (b * CM + c) * S + (d * 32 + h) * 32 + w0;
#pragma unroll
    for (int m = 0; m < 4; m++) {
        float a, bb; upk2(acc[m], a, bb);
        *(u64*)(dst + 2 * m) = pk2(a * scv + biv, bb * scv + biv);
    }
}

// ---------------- k3b: cv4 (32->216) + b4 + GN partial sums (R15 passing) ---
__global__ void __launch_bounds__(288) k3b_cv4(
        const float* __restrict__ w4, const float* __restrict__ b4) {
    extern __shared__ u64 sm[];
    u64* wp = sm;                                  // [c][72] = 2304 u64
    ulonglong2* apv = (ulonglong2*)(sm + 2304);    // [c][32] pairs (lane, lane+32)
    __shared__ float redsum[NG], redsq[NG];
    int t = threadIdx.x;
    int oc = blockIdx.x % 3;
    int sblk = blockIdx.x / 3;
    int kkbase = oc * 72;

    for (int i = t; i < 72 * CM; i += 288) {
        int c = i / 72, o = i - c * 72;
        float v = w4[(kkbase + o) * CM + c];
        wp[i] = pk2(v, v);
    }
    if (t < NG) { redsum[t] = 0.f; redsq[t] = 0.f; }

    int pos0 = sblk * 128;
    int b = pos0 >> 15, s = pos0 & (S - 1);
    for (int i = t; i < 1024; i += 288) {
        int c = i >> 5, ll = i & 31;
        const float* p = g_a1 + (b * CM + c) * S + s;
        ulonglong2 v;
        v.x = *(const u64*)(p + 2 * ll);
        v.y = *(const u64*)(p + 64 + 2 * ll);
        apv[i] = v;
    }
    __syncthreads();

    int warp = t >> 5, lane = t & 31;       // warp 0..8
    int kk0 = kkbase + warp * 8;

    u64 accA[8], accB[8];
#pragma unroll
    for (int o = 0; o < 8; o++) {
        float bv = __ldg(b4 + kk0 + o);
        accA[o] = pk2(bv, bv); accB[o] = pk2(bv, bv);
    }

    ulonglong2 aq = apv[lane];
    u64 wc_[8];
    {
        const ulonglong2* wv = (const ulonglong2*)(wp + warp * 8);
#pragma unroll
        for (int j = 0; j < 4; j++) { ulonglong2 v = wv[j]; wc_[2*j] = v.x; wc_[2*j+1] = v.y; }
    }
#pragma unroll
    for (int c = 0; c < CM - 1; c++) {
        ulonglong2 aqn = apv[(c + 1) * 32 + lane];
        u64 wn[8];
        {
            const ulonglong2* wv = (const ulonglong2*)(wp + (c + 1) * 72 + warp * 8);
#pragma unroll
            for (int j = 0; j < 4; j++) { ulonglong2 v = wv[j]; wn[2*j] = v.x; wn[2*j+1] = v.y; }
        }
#pragma unroll
        for (int o = 0; o < 8; o++) {
            fma2(accA[o], wc_[o], aq.x);
            fma2(accB[o], wc_[o], aq.y);
        }
        aq = aqn;
#pragma unroll
        for (int o = 0; o < 8; o++) wc_[o] = wn[o];
    }
#pragma unroll
    for (int o = 0; o < 8; o++) {           // last c
        fma2(accA[o], wc_[o], aq.x);
        fma2(accB[o], wc_[o], aq.y);
    }

    int g0 = kk0 / 27;
    int brk = (g0 + 1) * 27 - kk0;
    float su0 = 0.f, sq0 = 0.f, su1 = 0.f, sq1 = 0.f;
#pragma unroll
    for (int o = 0; o < 8; o++) {
        int kk = kk0 + o;
        float* dst = g_wk + (b * KCH + kk) * S + s;
        *(u64*)(dst + 2 * lane) = accA[o];
        *(u64*)(dst + 64 + 2 * lane) = accB[o];
        float a0, b0, a1, b1;
        upk2(accA[o], a0, b0); upk2(accB[o], a1, b1);
        float ss = a0 + b0 + a1 + b1;
        float qq = a0 * a0 + b0 * b0 + a1 * a1 + b1 * b1;
        if (o < brk) { su0 += ss; sq0 += qq; } else { su1 += ss; sq1 += qq; }
    }
#pragma unroll
    for (int off = 16; off; off >>= 1) {
        su0 += __shfl_down_sync(0xffffffffu, su0, off);
        sq0 += __shfl_down_sync(0xffffffffu, sq0, off);
        su1 += __shfl_down_sync(0xffffffffu, su1, off);
        sq1 += __shfl_down_sync(0xffffffffu, sq1, off);
    }
    if (lane == 0) {
        atomicAdd(&redsum[g0], su0); atomicAdd(&redsq[g0], sq0);
        if (brk < 8) { atomicAdd(&redsum[g0 + 1], su1); atomicAdd(&redsq[g0 + 1], sq1); }
    }
    __syncthreads();
    if (t < NG) {
        atomicAdd(&g_sum[b * NG + t], redsum[t]);
        atomicAdd(&g_sq [b * NG + t], redsq[t]);
    }
}

// ---------------- k4: finalize GN stats, then reset accumulators ------------
__global__ void k4_stats() {
    int i = threadIdx.x;
    if (i < NB * NG) {
        float n  = 27.f * (float)S;
        float mu = g_sum[i] / n;
        float var = g_sq[i] / n - mu * mu;
        g_mu[i] = mu;
        g_rstd[i] = rsqrtf(var + 1e-5f);
        g_sum[i] = 0.f;
        g_sq[i]  = 0.f;
    }
}

// ---------------- k5: GN affine + SKA (circular) + BN + residual, v3 --------
// Boundary neighbors v0/v5 now come from warp shuffles (lanes 8k..8k+7 share a
// row; wq = lane&7). Exchanged values are the identical fp32 bits the scalar
// LDGs fetched -> bitwise-identical output, 144 scattered LDGs removed.
__global__ void __launch_bounds__(256) k5_ska(
        const float* __restrict__ x,
        const float* __restrict__ gn_g, const float* __restrict__ gn_b,
        const float* __restrict__ bn_s, const float* __restrict__ bn_b) {
    int gid = blockIdx.x * blockDim.x + threadIdx.x;
    int wq = gid & 7;
    int h  = (gid >> 3) & 31;
    int d  = (gid >> 8) & 31;
    int g  = (gid >> 13) & 7;
    int b  = gid >> 16;
    int w0 = wq * 4;
    int sbase = (d * 32 + h) * 32 + w0;

    int lane = threadIdx.x & 31;
    int laneUp = (lane & ~7) | ((wq + 7) & 7);   // source of v0 (prev wq, wrap)
    int laneDn = (lane & ~7) | ((wq + 1) & 7);   // source of v5 (next wq, wrap)

    float mu = g_mu[b * NG + g], rs = g_rstd[b * NG + g];

    u64 accL[CPG], accH[CPG];
#pragma unroll
    for (int c = 0; c < CPG; c++) { accL[c] = 0ull; accH[c] = 0ull; }

    const float* xg = x + (b * CIN + g * CPG) * S;
    const float* wsrc = g_wk + (b * KCH + g * 27) * S + sbase;

    for (int dgi = 0; dgi < 3; dgi++) {
        int zd = (d + dgi - 1) & 31;
        u64 kvL[9], kvH[9];
#pragma unroll
        for (int j = 0; j < 9; j++) {
            int k = dgi * 9 + j;
            float4 q = *(const float4*)(wsrc + k * S);
            int ch = g * 27 + k;
            float gg = __ldg(gn_g + ch) * rs;
            float bb = __ldg(gn_b + ch) - mu * gg;
            kvL[j] = pk2(q.x * gg + bb, q.y * gg + bb);
            kvH[j] = pk2(q.z * gg + bb, q.w * gg + bb);
        }
#pragma unroll
        for (int c = 0; c < CPG; c++) {
            const float* xc = xg + c * S;
#pragma unroll
            for (int hi = 0; hi < 3; hi++) {
                int zh = (h + hi - 1) & 31;
                const float* row = xc + (zd * 32 + zh) * 32;
                float4 mid = *(const float4*)(row + w0);
                float v0 = __shfl_sync(0xffffffffu, mid.w, laneUp);
                float v5 = __shfl_sync(0xffffffffu, mid.x, laneDn);
                u64 p01 = pk2(v0,    mid.x);
                u64 p12 = pk2(mid.x, mid.y);
                u64 p23 = pk2(mid.y, mid.z);
                u64 p34 = pk2(mid.z, mid.w);
                u64 p45 = pk2(mid.w, v5);
                int j = hi * 3;
                fma2(accL[c], kvL[j + 0], p01);
                fma2(accL[c], kvL[j + 1], p12);
                fma2(accL[c], kvL[j + 2], p23);
                fma2(accH[c], kvH[j + 0], p23);
                fma2(accH[c], kvH[j + 1], p34);
                fma2(accH[c], kvH[j + 2], p45);
            }
        }
    }

    float* yg = g_y + (b * CIN + g * CPG) * S;
#pragma unroll
    for (int c = 0; c < CPG; c++) {
        float a0, a1v, a2v, a3v;
        upk2(accL[c], a0, a1v); upk2(accH[c], a2v, a3v);
        int ch = g * CPG + c;
        float bs_ = __ldg(bn_s + ch), bb_ = __ldg(bn_b + ch);
        float4 xq = *(const float4*)(xg + c * S + sbase);
        float4 r;
        r.x = a0  * bs_ + bb_ + xq.x;
        r.y = a1v * bs_ + bb_ + xq.y;
        r.z = a2v * bs_ + bb_ + xq.z;
        r.w = a3v * bs_ + bb_ + xq.w;
        *(float4*)(yg + c * S + sbase) = r;
    }
}

// ---------------- k6a: pw1 (64->128) + BN + ReLU (R15 passing, P=4) ---------
__global__ void __launch_bounds__(256) k6a_pw1(
        const float* __restrict__ w, const float* __restrict__ sc,
        const float* __restrict__ bi) {
    extern __shared__ u64 sm[];
    u64* wp = sm;                      // [c][64] chunk = 4096 u64 = 32KB
    int t = threadIdx.x;
    int oc = blockIdx.x & 1;
    int sblk = blockIdx.x >> 1;
    for (int i = t; i < 4096; i += 256) {
        int c = i >> 6, ol = i & 63;
        float v = w[(oc * 64 + ol) * 64 + c];
        wp[i] = pk2(v, v);
    }
    __syncthreads();

    int og = t >> 5, lane = t & 31;
    int pos0 = sblk * 256;
    int b = pos0 >> 15, s = pos0 & (S - 1);

    u64 acc0[8], acc1[8], acc2[8], acc3[8];
#pragma unroll
    for (int o = 0; o < 8; o++) { acc0[o] = 0ull; acc1[o] = 0ull; acc2[o] = 0ull; acc3[o] = 0ull; }

    const float* yb = g_y + b * CIN * S + s;
    ulonglong2 a0 = *(const ulonglong2*)(yb + 4 * lane);
    ulonglong2 a1 = *(const ulonglong2*)(yb + 128 + 4 * lane);
    u64 wc_[8];
    {
        const ulonglong2* wv = (const ulonglong2*)(wp + og * 8);
#pragma unroll
        for (int j = 0; j < 4; j++) { ulonglong2 v = wv[j]; wc_[2*j] = v.x; wc_[2*j+1] = v.y; }
    }
#pragma unroll 4
    for (int c = 0; c < CIN - 1; c++) {
        const float* yr = yb + (c + 1) * S;
        ulonglong2 a0n = *(const ulonglong2*)(yr + 4 * lane);
        ulonglong2 a1n = *(const ulonglong2*)(yr + 128 + 4 * lane);
        u64 wn[8];
        {
            const ulonglong2* wv = (const ulonglong2*)(wp + (c + 1) * 64 + og * 8);
#pragma unroll
            for (int j = 0; j < 4; j++) { ulonglong2 v = wv[j]; wn[2*j] = v.x; wn[2*j+1] = v.y; }
        }
#pragma unroll
        for (int o = 0; o < 8; o++) {
            fma2(acc0[o], wc_[o], a0.x);
            fma2(acc1[o], wc_[o], a0.y);
            fma2(acc2[o], wc_[o], a1.x);
            fma2(acc3[o], wc_[o], a1.y);
        }
        a0 = a0n; a1 = a1n;
#pragma unroll
        for (int o = 0; o < 8; o++) wc_[o] = wn[o];
    }
#pragma unroll
    for (int o = 0; o < 8; o++) {
        fma2(acc0[o], wc_[o], a0.x);
        fma2(acc1[o], wc_[o], a0.y);
        fma2(acc2[o], wc_[o], a1.x);
        fma2(acc3[o], wc_[o], a1.y);
    }

#pragma unroll
    for (int o = 0; o < 8; o++) {
        int oo = oc * 64 + og * 8 + o;
        float scv = __ldg(sc + oo), biv = __ldg(bi + oo);
        float a, bq;
        float* hb = g_h + (b * 128 + oo) * S + s;
        ulonglong2 r1;
        upk2(acc0[o], a, bq);
        r1.x = pk2(fmaxf(a * scv + biv, 0.f), fmaxf(bq * scv + biv, 0.f));
        upk2(acc1[o], a, bq);
        r1.y = pk2(fmaxf(a * scv + biv, 0.f), fmaxf(bq * scv + biv, 0.f));
        *(ulonglong2*)(hb + 4 * lane) = r1;
        ulonglong2 r2;
        upk2(acc2[o], a, bq);
        r2.x = pk2(fmaxf(a * scv + biv, 0.f), fmaxf(bq * scv + biv, 0.f));
        upk2(acc3[o], a, bq);
        r2.y = pk2(fmaxf(a * scv + biv, 0.f), fmaxf(bq * scv + biv, 0.f));
        *(ulonglong2*)(hb + 128 + 4 * lane) = r2;
    }
}

// ---------------- k6b: pw2 (128->64) + BN + add y -> out (R15 passing, P=4) -
__global__ void __launch_bounds__(256) k6b_pw2(
        const float* __restrict__ w, const float* __restrict__ sc,
        const float* __restrict__ bi, float* __restrict__ out) {
    extern __shared__ u64 sm[];
    u64* wp = sm;                      // [c][64] = 8192 u64 = 64KB
    int t = threadIdx.x;
    for (int i = t; i < 8192; i += 256) {
        int c = i >> 6, o = i & 63;
        float v = w[o * 128 + c];      // pw2_w [64][128] row-major
        wp[i] = pk2(v, v);
    }
    __syncthreads();

    int og = t >> 5, lane = t & 31;
    int pos0 = blockIdx.x * 256;
    int b = pos0 >> 15, s = pos0 & (S - 1);

    u64 acc0[8], acc1[8], acc2[8], acc3[8];
#pragma unroll
    for (int o = 0; o < 8; o++) { acc0[o] = 0ull; acc1[o] = 0ull; acc2[o] = 0ull; acc3[o] = 0ull; }

    const float* hb = g_h + b * 128 * S + s;
    ulonglong2 a0 = *(const ulonglong2*)(hb + 4 * lane);
    ulonglong2 a1 = *(const ulonglong2*)(hb + 128 + 4 * lane);
    u64 wc_[8];
    {
        const ulonglong2* wv = (const ulonglong2*)(wp + og * 8);
#pragma unroll
        for (int j = 0; j < 4; j++) { ulonglong2 v = wv[j]; wc_[2*j] = v.x; wc_[2*j+1] = v.y; }
    }
#pragma unroll 4
    for (int c = 0; c < 127; c++) {
        const float* hr = hb + (c + 1) * S;
        ulonglong2 a0n = *(const ulonglong2*)(hr + 4 * lane);
        ulonglong2 a1n = *(const ulonglong2*)(hr + 128 + 4 * lane);
        u64 wn[8];
        {
            const ulonglong2* wv = (const ulonglong2*)(wp + (c + 1) * 64 + og * 8);
#pragma unroll
            for (int j = 0; j < 4; j++) { ulonglong2 v = wv[j]; wn[2*j] = v.x; wn[2*j+1] = v.y; }
        }
#pragma unroll
        for (int o = 0; o < 8; o++) {
            fma2(acc0[o], wc_[o], a0.x);
            fma2(acc1[o], wc_[o], a0.y);
            fma2(acc2[o], wc_[o], a1.x);
            fma2(acc3[o], wc_[o], a1.y);
        }
        a0 = a0n; a1 = a1n;
#pragma unroll
        for (int o = 0; o < 8; o++) wc_[o] = wn[o];
    }
#pragma unroll
    for (int o = 0; o < 8; o++) {
        fma2(acc0[o], wc_[o], a0.x);
        fma2(acc1[o], wc_[o], a0.y);
        fma2(acc2[o], wc_[o], a1.x);
        fma2(acc3[o], wc_[o], a1.y);
    }

#pragma unroll
    for (int o = 0; o < 8; o++) {
        int oo = og * 8 + o;
        float scv = __ldg(sc + oo), biv = __ldg(bi + oo);
        const float* yb = g_y + (b * CIN + oo) * S + s;
        float* ob = out + (b * CIN + oo) * S + s;
        float a, bq, y0, y1;
        ulonglong2 yq = *(const ulonglong2*)(yb + 4 * lane);
        ulonglong2 r1;
        upk2(acc0[o], a, bq); upk2(yq.x, y0, y1);
        r1.x = pk2(y0 + a * scv + biv, y1 + bq * scv + biv);
        upk2(acc1[o], a, bq); upk2(yq.y, y0, y1);
        r1.y = pk2(y0 + a * scv + biv, y1 + bq * scv + biv);
        *(ulonglong2*)(ob + 4 * lane) = r1;
        ulonglong2 yq2 = *(const ulonglong2*)(yb + 128 + 4 * lane);
        ulonglong2 r2;
        upk2(acc2[o], a, bq); upk2(yq2.x, y0, y1);
        r2.x = pk2(y0 + a * scv + biv, y1 + bq * scv + biv);
        upk2(acc3[o], a, bq); upk2(yq2.y, y0, y1);
        r2.y = pk2(y0 + a * scv + biv, y1 + bq * scv + biv);
        *(ulonglong2*)(ob + 128 + 4 * lane) = r2;
    }
}

// ---------------- launcher ----------------
extern "C" void kernel_launch(void* const* d_in, const int* in_sizes, int n_in,
                              void* d_out, int out_size) {
    const float* x     = (const float*)d_in[0];
    const float* w1    = (const float*)d_in[1];
    const float* s1    = (const float*)d_in[2];
    const float* b1    = (const float*)d_in[3];
    const float* w2    = (const float*)d_in[4];
    const float* s2    = (const float*)d_in[5];
    const float* b2    = (const float*)d_in[6];
    const float* w3    = (const float*)d_in[7];
    const float* s3    = (const float*)d_in[8];
    const float* b3    = (const float*)d_in[9];
    const float* w4    = (const float*)d_in[10];
    const float* b4    = (const float*)d_in[11];
    const float* gn_g  = (const float*)d_in[12];
    const float* gn_b  = (const float*)d_in[13];
    const float* bn_s  = (const float*)d_in[14];
    const float* bn_b  = (const float*)d_in[15];
    const float* pw1_w = (const float*)d_in[16];
    const float* pw1_s = (const float*)d_in[17];
    const float* pw1_b = (const float*)d_in[18];
    const float* pw2_w = (const float*)d_in[19];
    const float* pw2_s = (const float*)d_in[20];
    const float* pw2_b = (const float*)d_in[21];
    float* out = (float*)d_out;

    const int smem_k3b = (2304 + 2048) * 8;          // 34 KB
    const int smem_k6a = 4096 * 8;                   // 32 KB
    const int smem_k6b = 8192 * 8;                   // 64 KB
    cudaFuncSetAttribute(k3b_cv4, cudaFuncAttributeMaxDynamicSharedMemorySize, smem_k3b);
    cudaFuncSetAttribute(k6a_pw1, cudaFuncAttributeMaxDynamicSharedMemorySize, smem_k6a);
    cudaFuncSetAttribute(k6b_pw2, cudaFuncAttributeMaxDynamicSharedMemorySize, smem_k6b);

    k1_cv1  <<<128, 256>>>(x, w1, s1, b1);
    k2_dw5  <<<2048, 128>>>(w2, s2, b2);
    k3a_cv3 <<<128, 256>>>(w3, s3, b3);
    k3b_cv4 <<<1536, 288, smem_k3b>>>(w4, b4);       // slot 3 <- profiled
    k4_stats<<<1, 32>>>();
    k5_ska  <<<512, 256>>>(x, gn_g, gn_b, bn_s, bn_b);
    k6a_pw1 <<<512, 256, smem_k6a>>>(pw1_w, pw1_s, pw1_b);
    k6b_pw2 <<<256, 256, smem_k6b>>>(pw2_w, pw2_s, pw2_b, out);
}

// round 17
// speedup vs baseline: 1.0487x; 1.0487x over previous
#include <cuda_runtime.h>

#define S   32768          // 32*32*32 spatial
#define NB  2              // batch
#define CIN 64
#define CM  32             // mid channels
#define KCH 216            // dynamic kernel channels
#define NG  8              // groups
#define CPG 8              // channels per group (64/8)

typedef unsigned long long u64;

// ---------------- f32x2 helpers ----------------
__device__ __forceinline__ u64 pk2(float a, float b) {
    u64 r; asm("mov.b64 %0,{%1,%2};" : "=l"(r) : "f"(a), "f"(b)); return r;
}
__device__ __forceinline__ void upk2(u64 v, float& a, float& b) {
    asm("mov.b64 {%0,%1},%2;" : "=f"(a), "=f"(b) : "l"(v));
}
__device__ __forceinline__ void fma2(u64& d, u64 a, u64 b) {
    asm("fma.rn.f32x2 %0,%1,%2,%0;" : "+l"(d) : "l"(a), "l"(b));
}

// ---------------- scratch (device globals; allocation-free) ----------------
__device__ float g_a1[NB * CM  * S];
__device__ float g_a2[NB * CM  * S];
__device__ float g_wk[NB * KCH * S];
__device__ float g_y [NB * CIN * S];
__device__ float g_h [NB * 128 * S];
__device__ float g_sum[NB * NG];       // zero-init; k4 re-zeros after use
__device__ float g_sq [NB * NG];
__device__ float g_mu [NB * NG];
__device__ float g_rstd[NB * NG];

// ---------------- cv body: K->32 1x1 conv + BN + ReLU --------------------
// v2 geometry: block 128 = 4 warps (og = warp&1, pset = warp>>1), 256 pos/block,
// grid 256 -> full-chip coverage + 2 blocks/SM. Same P=2, same c-order ->
// bitwise-identical arithmetic to the R13-passing version.
template<int K>
__device__ __forceinline__ void cv_body(
        const float* __restrict__ in, const float* __restrict__ w,
        const float* __restrict__ sc, const float* __restrict__ bi,
        float* __restrict__ outbuf) {
    __shared__ u64 ws[K * 32];       // [c][o]
    int t = threadIdx.x;
    for (int i = t; i < K * 32; i += 128) {
        int c = i >> 5, o = i & 31;
        float v = w[o * K + c];
        ws[i] = pk2(v, v);
    }
    __syncthreads();

    int warp = t >> 5, lane = t & 31;
    int og = warp & 1, pset = warp >> 1;       // og 0..1, pset 0..1
    int pr = pset * 32 + lane;                 // 0..63
    int pos0 = blockIdx.x * 256;
    int b = pos0 >> 15, s = pos0 & (S - 1);
    int sA = s + 2 * pr;
    int sB = sA + 128;

    u64 accA[16], accB[16];
#pragma unroll
    for (int o = 0; o < 16; o++) { accA[o] = 0ull; accB[o] = 0ull; }

    const float* ib = in + b * K * S;
#pragma unroll 2
    for (int c = 0; c < K; c++) {
        u64 xqA = *(const u64*)(ib + c * S + sA);
        u64 xqB = *(const u64*)(ib + c * S + sB);
        const ulonglong2* wv = (const ulonglong2*)(ws + c * 32 + og * 16);
#pragma unroll
        for (int j = 0; j < 8; j++) {
            ulonglong2 wq = wv[j];
            fma2(accA[2 * j], wq.x, xqA);
            fma2(accB[2 * j], wq.x, xqB);
            fma2(accA[2 * j + 1], wq.y, xqA);
            fma2(accB[2 * j + 1], wq.y, xqB);
        }
    }
#pragma unroll
    for (int o = 0; o < 16; o++) {
        int oo = og * 16 + o;
        float scv = __ldg(sc + oo), biv = __ldg(bi + oo);
        float a, bq;
        float* ob = outbuf + (b * CM + oo) * S;
        upk2(accA[o], a, bq);
        *(u64*)(ob + sA) = pk2(fmaxf(a * scv + biv, 0.f), fmaxf(bq * scv + biv, 0.f));
        upk2(accB[o], a, bq);
        *(u64*)(ob + sB) = pk2(fmaxf(a * scv + biv, 0.f), fmaxf(bq * scv + biv, 0.f));
    }
}

__global__ void __launch_bounds__(128) k1_cv1(
        const float* __restrict__ x, const float* __restrict__ w1,
        const float* __restrict__ s1, const float* __restrict__ b1) {
    cv_body<64>(x, w1, s1, b1, g_a1);
}

__global__ void __launch_bounds__(128) k3a_cv3(
        const float* __restrict__ w3, const float* __restrict__ s3,
        const float* __restrict__ b3) {
    cv_body<32>(g_a2, w3, s3, b3, g_a1);
}

// ---------------- k2: depthwise 5x5x5 (zero pad) + BN, f32x2 (passing) ------
__global__ void __launch_bounds__(128) k2_dw5(
        const float* __restrict__ w2, const float* __restrict__ s2,
        const float* __restrict__ b2) {
    int blk = blockIdx.x;
    int d = blk & 31;
    int c = (blk >> 5) & 31;
    int b = blk >> 10;
    int t = threadIdx.x;
    int wq = t & 3, h = t >> 2;
    int w0 = wq * 8;

    const float* src = g_a1 + (b * CM + c) * S;
    const float* wc  = w2 + c * 125;
    const float4 zero4 = make_float4(0.f, 0.f, 0.f, 0.f);

    u64 acc[4];
#pragma unroll
    for (int m = 0; m < 4; m++) acc[m] = 0ull;

    for (int dd = 0; dd < 5; dd++) {
        int zd = d + dd - 2;
        if ((unsigned)zd >= 32u) continue;
        for (int dh = 0; dh < 5; dh++) {
            int zh = h + dh - 2;
            if ((unsigned)zh >= 32u) continue;
            const float* row = src + (zd * 32 + zh) * 32;
            float4 f0 = (wq > 0) ? *(const float4*)(row + w0 - 4) : zero4;
            float4 f1 = *(const float4*)(row + w0);
            float4 f2 = *(const float4*)(row + w0 + 4);
            float4 f3 = (wq < 3) ? *(const float4*)(row + w0 + 8) : zero4;
            u64 A0 = pk2(f0.z, f0.w), A1 = pk2(f1.x, f1.y), A2 = pk2(f1.z, f1.w);
            u64 A3 = pk2(f2.x, f2.y), A4 = pk2(f2.z, f2.w), A5 = pk2(f3.x, f3.y);
            u64 M0 = pk2(f0.w, f1.x), M1 = pk2(f1.y, f1.z), M2 = pk2(f1.w, f2.x);
            u64 M3 = pk2(f2.y, f2.z), M4 = pk2(f2.w, f3.x);
            const float* wr = wc + (dd * 5 + dh) * 5;
            u64 T0 = pk2(wr[0], wr[0]), T1 = pk2(wr[1], wr[1]), T2 = pk2(wr[2], wr[2]);
            u64 T3 = pk2(wr[3], wr[3]), T4 = pk2(wr[4], wr[4]);
            fma2(acc[0], T0, A0); fma2(acc[0], T1, M0); fma2(acc[0], T2, A1);
            fma2(acc[0], T3, M1); fma2(acc[0], T4, A2);
            fma2(acc[1], T0, A1); fma2(acc[1], T1, M1); fma2(acc[1], T2, A2);
            fma2(acc[1], T3, M2); fma2(acc[1], T4, A3);
            fma2(acc[2], T0, A2); fma2(acc[2], T1, M2); fma2(acc[2], T2, A3);
            fma2(acc[2], T3, M3); fma2(acc[2], T4, A4);
            fma2(acc[3], T0, A3); fma2(acc[3], T1, M3); fma2(acc[3], T2, A4);
            fma2(acc[3], T3, M4); fma2(acc[3], T4, A5);
        }
    }
    float scv = s2[c], biv = b2[c];
    float* dst = g_a2 + (b * CM + c) * S + (d * 32 + h) * 32 + w0;
#pragma unroll
    for (int m = 0; m < 4; m++) {
        float a, bb; upk2(acc[m], a, bb);
        *(u64*)(dst + 2 * m) = pk2(a * scv + biv, bb * scv + biv);
    }
}

// ---------------- k3b: cv4 (32->216) + b4 + GN partial sums (R13 passing) ---
__global__ void __launch_bounds__(288) k3b_cv4(
        const float* __restrict__ w4, const float* __restrict__ b4) {
    extern __shared__ u64 sm[];
    u64* wp = sm;                                  // [c][72] = 2304 u64
    ulonglong2* apv = (ulonglong2*)(sm + 2304);    // [c][32] pairs (lane, lane+32)
    __shared__ float redsum[NG], redsq[NG];
    int t = threadIdx.x;
    int oc = blockIdx.x % 3;
    int sblk = blockIdx.x / 3;
    int kkbase = oc * 72;

    for (int i = t; i < 72 * CM; i += 288) {
        int c = i / 72, o = i - c * 72;
        float v = w4[(kkbase + o) * CM + c];
        wp[i] = pk2(v, v);
    }
    if (t < NG) { redsum[t] = 0.f; redsq[t] = 0.f; }

    int pos0 = sblk * 128;
    int b = pos0 >> 15, s = pos0 & (S - 1);
    for (int i = t; i < 1024; i += 288) {
        int c = i >> 5, ll = i & 31;
        const float* p = g_a1 + (b * CM + c) * S + s;
        ulonglong2 v;
        v.x = *(const u64*)(p + 2 * ll);
        v.y = *(const u64*)(p + 64 + 2 * ll);
        apv[i] = v;
    }
    __syncthreads();

    int warp = t >> 5, lane = t & 31;       // warp 0..8
    int kk0 = kkbase + warp * 8;

    u64 accA[8], accB[8];
#pragma unroll
    for (int o = 0; o < 8; o++) {
        float bv = __ldg(b4 + kk0 + o);
        accA[o] = pk2(bv, bv); accB[o] = pk2(bv, bv);
    }

    ulonglong2 aq = apv[lane];
    u64 wc_[8];
    {
        const ulonglong2* wv = (const ulonglong2*)(wp + warp * 8);
#pragma unroll
        for (int j = 0; j < 4; j++) { ulonglong2 v = wv[j]; wc_[2*j] = v.x; wc_[2*j+1] = v.y; }
    }
#pragma unroll
    for (int c = 0; c < CM - 1; c++) {
        ulonglong2 aqn = apv[(c + 1) * 32 + lane];
        u64 wn[8];
        {
            const ulonglong2* wv = (const ulonglong2*)(wp + (c + 1) * 72 + warp * 8);
#pragma unroll
            for (int j = 0; j < 4; j++) { ulonglong2 v = wv[j]; wn[2*j] = v.x; wn[2*j+1] = v.y; }
        }
#pragma unroll
        for (int o = 0; o < 8; o++) {
            fma2(accA[o], wc_[o], aq.x);
            fma2(accB[o], wc_[o], aq.y);
        }
        aq = aqn;
#pragma unroll
        for (int o = 0; o < 8; o++) wc_[o] = wn[o];
    }
#pragma unroll
    for (int o = 0; o < 8; o++) {           // last c
        fma2(accA[o], wc_[o], aq.x);
        fma2(accB[o], wc_[o], aq.y);
    }

    int g0 = kk0 / 27;
    int brk = (g0 + 1) * 27 - kk0;
    float su0 = 0.f, sq0 = 0.f, su1 = 0.f, sq1 = 0.f;
#pragma unroll
    for (int o = 0; o < 8; o++) {
        int kk = kk0 + o;
        float* dst = g_wk + (b * KCH + kk) * S + s;
        *(u64*)(dst + 2 * lane) = accA[o];
        *(u64*)(dst + 64 + 2 * lane) = accB[o];
        float a0, b0, a1, b1;
        upk2(accA[o], a0, b0); upk2(accB[o], a1, b1);
        float ss = a0 + b0 + a1 + b1;
        float qq = a0 * a0 + b0 * b0 + a1 * a1 + b1 * b1;
        if (o < brk) { su0 += ss; sq0 += qq; } else { su1 += ss; sq1 += qq; }
    }
#pragma unroll
    for (int off = 16; off; off >>= 1) {
        su0 += __shfl_down_sync(0xffffffffu, su0, off);
        sq0 += __shfl_down_sync(0xffffffffu, sq0, off);
        su1 += __shfl_down_sync(0xffffffffu, su1, off);
        sq1 += __shfl_down_sync(0xffffffffu, sq1, off);
    }
    if (lane == 0) {
        atomicAdd(&redsum[g0], su0); atomicAdd(&redsq[g0], sq0);
        if (brk < 8) { atomicAdd(&redsum[g0 + 1], su1); atomicAdd(&redsq[g0 + 1], sq1); }
    }
    __syncthreads();
    if (t < NG) {
        atomicAdd(&g_sum[b * NG + t], redsum[t]);
        atomicAdd(&g_sq [b * NG + t], redsq[t]);
    }
}

// ---------------- k4: finalize GN stats, then reset accumulators ------------
__global__ void k4_stats() {
    int i = threadIdx.x;
    if (i < NB * NG) {
        float n  = 27.f * (float)S;
        float mu = g_sum[i] / n;
        float var = g_sq[i] / n - mu * mu;
        g_mu[i] = mu;
        g_rstd[i] = rsqrtf(var + 1e-5f);
        g_sum[i] = 0.f;
        g_sq[i]  = 0.f;
    }
}

// ---------------- k5: GN affine + SKA (circular) + BN + residual (R13) ------
__global__ void __launch_bounds__(128) k5_ska(
        const float* __restrict__ x,
        const float* __restrict__ gn_g, const float* __restrict__ gn_b,
        const float* __restrict__ bn_s, const float* __restrict__ bn_b) {
    int gid = blockIdx.x * blockDim.x + threadIdx.x;
    int wq = gid & 7;
    int h  = (gid >> 3) & 31;
    int d  = (gid >> 8) & 31;
    int g  = (gid >> 13) & 7;
    int b  = gid >> 16;
    int w0 = wq * 4;
    int sbase = (d * 32 + h) * 32 + w0;

    float mu = g_mu[b * NG + g], rs = g_rstd[b * NG + g];

    u64 accL[CPG], accH[CPG];
#pragma unroll
    for (int c = 0; c < CPG; c++) { accL[c] = 0ull; accH[c] = 0ull; }

    const float* xg = x + (b * CIN + g * CPG) * S;
    const float* wsrc = g_wk + (b * KCH + g * 27) * S + sbase;

    for (int dgi = 0; dgi < 3; dgi++) {
        int zd = (d + dgi - 1) & 31;
        u64 kvL[9], kvH[9];
#pragma unroll
        for (int j = 0; j < 9; j++) {
            int k = dgi * 9 + j;
            float4 q = *(const float4*)(wsrc + k * S);
            int ch = g * 27 + k;
            float gg = __ldg(gn_g + ch) * rs;
            float bb = __ldg(gn_b + ch) - mu * gg;
            kvL[j] = pk2(q.x * gg + bb, q.y * gg + bb);
            kvH[j] = pk2(q.z * gg + bb, q.w * gg + bb);
        }
#pragma unroll
        for (int c = 0; c < CPG; c++) {
            const float* xc = xg + c * S;
#pragma unroll
            for (int hi = 0; hi < 3; hi++) {
                int zh = (h + hi - 1) & 31;
                const float* row = xc + (zd * 32 + zh) * 32;
                float4 mid = *(const float4*)(row + w0);
                float v0 = row[(w0 - 1) & 31];
                float v5 = row[(w0 + 4) & 31];
                u64 p01 = pk2(v0,    mid.x);
                u64 p12 = pk2(mid.x, mid.y);
                u64 p23 = pk2(mid.y, mid.z);
                u64 p34 = pk2(mid.z, mid.w);
                u64 p45 = pk2(mid.w, v5);
                int j = hi * 3;
                fma2(accL[c], kvL[j + 0], p01);
                fma2(accL[c], kvL[j + 1], p12);
                fma2(accL[c], kvL[j + 2], p23);
                fma2(accH[c], kvH[j + 0], p23);
                fma2(accH[c], kvH[j + 1], p34);
                fma2(accH[c], kvH[j + 2], p45);
            }
        }
    }

    float* yg = g_y + (b * CIN + g * CPG) * S;
#pragma unroll
    for (int c = 0; c < CPG; c++) {
        float a0, a1v, a2v, a3v;
        upk2(accL[c], a0, a1v); upk2(accH[c], a2v, a3v);
        int ch = g * CPG + c;
        float bs_ = __ldg(bn_s + ch), bb_ = __ldg(bn_b + ch);
        float4 xq = *(const float4*)(xg + c * S + sbase);
        float4 r;
        r.x = a0  * bs_ + bb_ + xq.x;
        r.y = a1v * bs_ + bb_ + xq.y;
        r.z = a2v * bs_ + bb_ + xq.z;
        r.w = a3v * bs_ + bb_ + xq.w;
        *(float4*)(yg + c * S + sbase) = r;
    }
}

// ---------------- k6a: pw1 (64->128) + BN + ReLU (R13 passing, P=4) ---------
__global__ void __launch_bounds__(256) k6a_pw1(
        const float* __restrict__ w, const float* __restrict__ sc,
        const float* __restrict__ bi) {
    extern __shared__ u64 sm[];
    u64* wp = sm;                      // [c][64] chunk = 4096 u64 = 32KB
    int t = threadIdx.x;
    int oc = blockIdx.x & 1;
    int sblk = blockIdx.x >> 1;
    for (int i = t; i < 4096; i += 256) {
        int c = i >> 6, ol = i & 63;
        float v = w[(oc * 64 + ol) * 64 + c];
        wp[i] = pk2(v, v);
    }
    __syncthreads();

    int og = t >> 5, lane = t & 31;
    int pos0 = sblk * 256;
    int b = pos0 >> 15, s = pos0 & (S - 1);

    u64 acc0[8], acc1[8], acc2[8], acc3[8];
#pragma unroll
    for (int o = 0; o < 8; o++) { acc0[o] = 0ull; acc1[o] = 0ull; acc2[o] = 0ull; acc3[o] = 0ull; }

    const float* yb = g_y + b * CIN * S + s;
    ulonglong2 a0 = *(const ulonglong2*)(yb + 4 * lane);
    ulonglong2 a1 = *(const ulonglong2*)(yb + 128 + 4 * lane);
    u64 wc_[8];
    {
        const ulonglong2* wv = (const ulonglong2*)(wp + og * 8);
#pragma unroll
        for (int j = 0; j < 4; j++) { ulonglong2 v = wv[j]; wc_[2*j] = v.x; wc_[2*j+1] = v.y; }
    }
#pragma unroll 4
    for (int c = 0; c < CIN - 1; c++) {
        const float* yr = yb + (c + 1) * S;
        ulonglong2 a0n = *(const ulonglong2*)(yr + 4 * lane);
        ulonglong2 a1n = *(const ulonglong2*)(yr + 128 + 4 * lane);
        u64 wn[8];
        {
            const ulonglong2* wv = (const ulonglong2*)(wp + (c + 1) * 64 + og * 8);
#pragma unroll
            for (int j = 0; j < 4; j++) { ulonglong2 v = wv[j]; wn[2*j] = v.x; wn[2*j+1] = v.y; }
        }
#pragma unroll
        for (int o = 0; o < 8; o++) {
            fma2(acc0[o], wc_[o], a0.x);
            fma2(acc1[o], wc_[o], a0.y);
            fma2(acc2[o], wc_[o], a1.x);
            fma2(acc3[o], wc_[o], a1.y);
        }
        a0 = a0n; a1 = a1n;
#pragma unroll
        for (int o = 0; o < 8; o++) wc_[o] = wn[o];
    }
#pragma unroll
    for (int o = 0; o < 8; o++) {
        fma2(acc0[o], wc_[o], a0.x);
        fma2(acc1[o], wc_[o], a0.y);
        fma2(acc2[o], wc_[o], a1.x);
        fma2(acc3[o], wc_[o], a1.y);
    }

#pragma unroll
    for (int o = 0; o < 8; o++) {
        int oo = oc * 64 + og * 8 + o;
        float scv = __ldg(sc + oo), biv = __ldg(bi + oo);
        float a, bq;
        float* hb = g_h + (b * 128 + oo) * S + s;
        ulonglong2 r1;
        upk2(acc0[o], a, bq);
        r1.x = pk2(fmaxf(a * scv + biv, 0.f), fmaxf(bq * scv + biv, 0.f));
        upk2(acc1[o], a, bq);
        r1.y = pk2(fmaxf(a * scv + biv, 0.f), fmaxf(bq * scv + biv, 0.f));
        *(ulonglong2*)(hb + 4 * lane) = r1;
        ulonglong2 r2;
        upk2(acc2[o], a, bq);
        r2.x = pk2(fmaxf(a * scv + biv, 0.f), fmaxf(bq * scv + biv, 0.f));
        upk2(acc3[o], a, bq);
        r2.y = pk2(fmaxf(a * scv + biv, 0.f), fmaxf(bq * scv + biv, 0.f));
        *(ulonglong2*)(hb + 128 + 4 * lane) = r2;
    }
}

// ---------------- k6b: pw2 (128->64) + BN + add y -> out (R13 passing, P=4) -
__global__ void __launch_bounds__(256) k6b_pw2(
        const float* __restrict__ w, const float* __restrict__ sc,
        const float* __restrict__ bi, float* __restrict__ out) {
    extern __shared__ u64 sm[];
    u64* wp = sm;                      // [c][64] = 8192 u64 = 64KB
    int t = threadIdx.x;
    for (int i = t; i < 8192; i += 256) {
        int c = i >> 6, o = i & 63;
        float v = w[o * 128 + c];      // pw2_w [64][128] row-major
        wp[i] = pk2(v, v);
    }
    __syncthreads();

    int og = t >> 5, lane = t & 31;
    int pos0 = blockIdx.x * 256;
    int b = pos0 >> 15, s = pos0 & (S - 1);

    u64 acc0[8], acc1[8], acc2[8], acc3[8];
#pragma unroll
    for (int o = 0; o < 8; o++) { acc0[o] = 0ull; acc1[o] = 0ull; acc2[o] = 0ull; acc3[o] = 0ull; }

    const float* hb = g_h + b * 128 * S + s;
    ulonglong2 a0 = *(const ulonglong2*)(hb + 4 * lane);
    ulonglong2 a1 = *(const ulonglong2*)(hb + 128 + 4 * lane);
    u64 wc_[8];
    {
        const ulonglong2* wv = (const ulonglong2*)(wp + og * 8);
#pragma unroll
        for (int j = 0; j < 4; j++) { ulonglong2 v = wv[j]; wc_[2*j] = v.x; wc_[2*j+1] = v.y; }
    }
#pragma unroll 4
    for (int c = 0; c < 127; c++) {
        const float* hr = hb + (c + 1) * S;
        ulonglong2 a0n = *(const ulonglong2*)(hr + 4 * lane);
        ulonglong2 a1n = *(const ulonglong2*)(hr + 128 + 4 * lane);
        u64 wn[8];
        {
            const ulonglong2* wv = (const ulonglong2*)(wp + (c + 1) * 64 + og * 8);
#pragma unroll
            for (int j = 0; j < 4; j++) { ulonglong2 v = wv[j]; wn[2*j] = v.x; wn[2*j+1] = v.y; }
        }
#pragma unroll
        for (int o = 0; o < 8; o++) {
            fma2(acc0[o], wc_[o], a0.x);
            fma2(acc1[o], wc_[o], a0.y);
            fma2(acc2[o], wc_[o], a1.x);
            fma2(acc3[o], wc_[o], a1.y);
        }
        a0 = a0n; a1 = a1n;
#pragma unroll
        for (int o = 0; o < 8; o++) wc_[o] = wn[o];
    }
#pragma unroll
    for (int o = 0; o < 8; o++) {
        fma2(acc0[o], wc_[o], a0.x);
        fma2(acc1[o], wc_[o], a0.y);
        fma2(acc2[o], wc_[o], a1.x);
        fma2(acc3[o], wc_[o], a1.y);
    }

#pragma unroll
    for (int o = 0; o < 8; o++) {
        int oo = og * 8 + o;
        float scv = __ldg(sc + oo), biv = __ldg(bi + oo);
        const float* yb = g_y + (b * CIN + oo) * S + s;
        float* ob = out + (b * CIN + oo) * S + s;
        float a, bq, y0, y1;
        ulonglong2 yq = *(const ulonglong2*)(yb + 4 * lane);
        ulonglong2 r1;
        upk2(acc0[o], a, bq); upk2(yq.x, y0, y1);
        r1.x = pk2(y0 + a * scv + biv, y1 + bq * scv + biv);
        upk2(acc1[o], a, bq); upk2(yq.y, y0, y1);
        r1.y = pk2(y0 + a * scv + biv, y1 + bq * scv + biv);
        *(ulonglong2*)(ob + 4 * lane) = r1;
        ulonglong2 yq2 = *(const ulonglong2*)(yb + 128 + 4 * lane);
        ulonglong2 r2;
        upk2(acc2[o], a, bq); upk2(yq2.x, y0, y1);
        r2.x = pk2(y0 + a * scv + biv, y1 + bq * scv + biv);
        upk2(acc3[o], a, bq); upk2(yq2.y, y0, y1);
        r2.y = pk2(y0 + a * scv + biv, y1 + bq * scv + biv);
        *(ulonglong2*)(ob + 128 + 4 * lane) = r2;
    }
}

// ---------------- launcher ----------------
extern "C" void kernel_launch(void* const* d_in, const int* in_sizes, int n_in,
                              void* d_out, int out_size) {
    const float* x     = (const float*)d_in[0];
    const float* w1    = (const float*)d_in[1];
    const float* s1    = (const float*)d_in[2];
    const float* b1    = (const float*)d_in[3];
    const float* w2    = (const float*)d_in[4];
    const float* s2    = (const float*)d_in[5];
    const float* b2    = (const float*)d_in[6];
    const float* w3    = (const float*)d_in[7];
    const float* s3    = (const float*)d_in[8];
    const float* b3    = (const float*)d_in[9];
    const float* w4    = (const float*)d_in[10];
    const float* b4    = (const float*)d_in[11];
    const float* gn_g  = (const float*)d_in[12];
    const float* gn_b  = (const float*)d_in[13];
    const float* bn_s  = (const float*)d_in[14];
    const float* bn_b  = (const float*)d_in[15];
    const float* pw1_w = (const float*)d_in[16];
    const float* pw1_s = (const float*)d_in[17];
    const float* pw1_b = (const float*)d_in[18];
    const float* pw2_w = (const float*)d_in[19];
    const float* pw2_s = (const float*)d_in[20];
    const float* pw2_b = (const float*)d_in[21];
    float* out = (float*)d_out;

    const int smem_k3b = (2304 + 2048) * 8;          // 34 KB
    const int smem_k6a = 4096 * 8;                   // 32 KB
    const int smem_k6b = 8192 * 8;                   // 64 KB
    cudaFuncSetAttribute(k3b_cv4, cudaFuncAttributeMaxDynamicSharedMemorySize, smem_k3b);
    cudaFuncSetAttribute(k6a_pw1, cudaFuncAttributeMaxDynamicSharedMemorySize, smem_k6a);
    cudaFuncSetAttribute(k6b_pw2, cudaFuncAttributeMaxDynamicSharedMemorySize, smem_k6b);

    k1_cv1  <<<256, 128>>>(x, w1, s1, b1);           // full-chip coverage
    k2_dw5  <<<2048, 128>>>(w2, s2, b2);
    k3a_cv3 <<<256, 128>>>(w3, s3, b3);
    k3b_cv4 <<<1536, 288, smem_k3b>>>(w4, b4);       // slot 3 <- profiled
    k4_stats<<<1, 32>>>();
    k5_ska  <<<1024, 128>>>(x, gn_g, gn_b, bn_s, bn_b);  // R13 exact
    k6a_pw1 <<<512, 256, smem_k6a>>>(pw1_w, pw1_s, pw1_b);
    k6b_pw2 <<<256, 256, smem_k6b>>>(pw2_w, pw2_s, pw2_b, out);
}